// round 13
// baseline (speedup 1.0000x reference)
#include <cuda_runtime.h>
#include <cuda_fp16.h>

#define BB 32
#define NN 1024
#define GG 8
#define HH 128

// ---- prepped B operands in EXACT mma fragment order ----
// entry (ck, nfp, lane) = 16B = {b0(nf0), b1(nf0), b0(nf0+1), b1(nf0+1)},
// nf0 = 2*nfp; b0 lane l = {B[ck*16+2*(l&3)][c], B[..+1][c]}, c = nfp*16+(l>>2); b1: k+8.
__device__ __align__(16) unsigned gBf[65536];   // W0 dots rows (256KB)
__device__ __align__(16) unsigned gW1f[8192];   // 32KB
__device__ __align__(16) unsigned gW2f[8192];

// ---- smem map (bytes) ----
#define OFF_BJ   0        // dot B-frag image 16KB (layer0; overlaps H)
#define OFF_H    0        // h plane (128x128 fp16, 256B rows) 32KB (layer phase)
#define OFF_AF   32768    // af exchange: 4 pairs x 2 slots x 2 warps x 512B = 8KB
#define OFF_XALL 40960    // x[b] fp32 [1024][3]
#define OFF_NRM  53248
#define OFF_CU   53760
#define OFF_W0N  54272
#define OFF_B1S  54784
#define OFF_B2S  55296
#define OFF_OACC 55808    // fp32 [128][3]
#define SMEM_BYTES 57344

// ---------------- helpers ----------------
__device__ __forceinline__ unsigned smem_u32(const void* p) {
    unsigned a;
    asm("{ .reg .u64 t; cvta.to.shared.u64 t, %1; cvt.u32.u64 %0, t; }" : "=r"(a) : "l"(p));
    return a;
}
__device__ __forceinline__ void ldsm_x4(unsigned* r, unsigned a) {
    asm volatile("ldmatrix.sync.aligned.m8n8.x4.shared.b16 {%0,%1,%2,%3}, [%4];"
                 : "=r"(r[0]), "=r"(r[1]), "=r"(r[2]), "=r"(r[3]) : "r"(a));
}
__device__ __forceinline__ void mma16816(float* d, const unsigned* a, unsigned b0, unsigned b1) {
    asm volatile(
        "mma.sync.aligned.m16n8k16.row.col.f32.f16.f16.f32 "
        "{%0,%1,%2,%3}, {%4,%5,%6,%7}, {%8,%9}, {%0,%1,%2,%3};"
        : "+f"(d[0]), "+f"(d[1]), "+f"(d[2]), "+f"(d[3])
        : "r"(a[0]), "r"(a[1]), "r"(a[2]), "r"(a[3]), "r"(b0), "r"(b1));
}
__device__ __forceinline__ void mma16808(float* d, unsigned a0, unsigned a1, unsigned b0) {
    asm volatile(
        "mma.sync.aligned.m16n8k8.row.col.f32.f16.f16.f32 "
        "{%0,%1,%2,%3}, {%4,%5}, {%6}, {%0,%1,%2,%3};"
        : "+f"(d[0]), "+f"(d[1]), "+f"(d[2]), "+f"(d[3])
        : "r"(a0), "r"(a1), "r"(b0));
}
__device__ __forceinline__ float asqrt(float v) {
    float r;
    asm("sqrt.approx.f32 %0, %1;" : "=f"(r) : "f"(v));
    return r;
}
__device__ __forceinline__ float leaky(float v) { return v > 0.0f ? v : 0.01f * v; }
__device__ __forceinline__ unsigned short h16(float v) {
    __half h = __float2half_rn(v);
    return *(unsigned short*)&h;
}
__device__ __forceinline__ unsigned pack2(float a, float b) {
    __half2 h = __floats2half2_rn(a, b);
    return *(unsigned*)&h;
}
__device__ __forceinline__ void barp(int id) {       // per-pair named barrier, 2 warps
    asm volatile("bar.sync %0, 64;" :: "r"(id) : "memory");
}
__device__ __forceinline__ void sts128(unsigned a, const unsigned* v) {
    asm volatile("st.shared.v4.b32 [%0], {%1,%2,%3,%4};"
                 :: "r"(a), "r"(v[0]), "r"(v[1]), "r"(v[2]), "r"(v[3]) : "memory");
}
__device__ __forceinline__ void lds128(unsigned* v, unsigned a) {
    asm volatile("ld.shared.v4.u32 {%0,%1,%2,%3}, [%4];"
                 : "=r"(v[0]), "=r"(v[1]), "=r"(v[2]), "=r"(v[3]) : "r"(a));
}

// Epilogue (4x2): leaky + fp16 into h plane (256B rows), re-init acc with bias.
__device__ __forceinline__ void epi_split(float (&acc)[16][4], unsigned char* dH,
                                          const float* nb, int rg, int cg, int lane) {
    const int cp = lane & 3, r8 = lane >> 2;
    #pragma unroll
    for (int m = 0; m < 2; m++) {
        const int r1 = rg * 32 + m * 16 + r8, r2 = r1 + 8;
        #pragma unroll
        for (int nfl = 0; nfl < 8; nfl++) {
            float* A = acc[m * 8 + nfl];
            const int c = cg * 64 + nfl * 8 + cp * 2;
            unsigned short a0 = h16(leaky(A[0])), a1 = h16(leaky(A[1]));
            unsigned short a2 = h16(leaky(A[2])), a3 = h16(leaky(A[3]));
            const unsigned o1 = r1 * 256 + ((unsigned)(((c >> 3) ^ (r1 & 7))) << 4) + (c & 7) * 2;
            const unsigned o2 = r2 * 256 + ((unsigned)(((c >> 3) ^ (r2 & 7))) << 4) + (c & 7) * 2;
            *(unsigned*)(dH + o1) = (unsigned)a0 | ((unsigned)a1 << 16);
            *(unsigned*)(dH + o2) = (unsigned)a2 | ((unsigned)a3 << 16);
            A[0] = nb[c]; A[1] = nb[c + 1]; A[2] = nb[c]; A[3] = nb[c + 1];
        }
    }
}

// ---------------------------------------------------------------------------
// Prep (+ output zero): rewrite weights into mma B-fragment order.
__global__ void k_prep(const float* __restrict__ W0, const float* __restrict__ W1,
                       const float* __restrict__ W2, float* __restrict__ out) {
    const int idx = blockIdx.x * 256 + threadIdx.x;
    const float* src; unsigned* dst; int t;
    if (idx < 65536)      { src = W0 + 9 * HH; dst = gBf;  t = idx; }
    else if (idx < 73728) { src = W1;          dst = gW1f; t = idx - 65536; }
    else if (idx < 81920) { src = W2;          dst = gW2f; t = idx - 73728; }
    else {
        int z = idx - 81920;
        if (z < BB * HH * 3) out[z] = 0.0f;
        return;
    }
    const int e = t >> 2, wsel = t & 3;
    const int ck = e >> 8, nfp = (e >> 5) & 7, l = e & 31;
    const int k0  = ck * 16 + 2 * (l & 3) + ((wsel & 1) ? 8 : 0);
    const int col = nfp * 16 + ((wsel >> 1) ? 8 : 0) + (l >> 2);
    const float v0 = src[(size_t)k0 * HH + col];
    const float v1 = src[(size_t)(k0 + 1) * HH + col];
    dst[t] = (unsigned)h16(v0) | ((unsigned)h16(v1) << 16);
}

// ---------------------------------------------------------------------------
__global__ void __launch_bounds__(256, 2)
k_main(const float* __restrict__ x, const float* __restrict__ u,
       const float* __restrict__ W0, const float* __restrict__ b0,
       const float* __restrict__ b1, const float* __restrict__ b2,
       float* __restrict__ out)
{
    extern __shared__ __align__(1024) unsigned char smem[];
    const unsigned sb = smem_u32(smem);
    const int tid = threadIdx.x, w = tid >> 5, lane = tid & 31;
    const int rg = w >> 1, cg = w & 1;          // pair = (rg), partner differs in cg
    const int b = blockIdx.x >> 3, i0 = (blockIdx.x & 7) * 128;
    const int il = lane & 15, kq = lane >> 4;

    float* xall = (float*)(smem + OFF_XALL);
    float* nrm  = (float*)(smem + OFF_NRM);
    float* cu   = (float*)(smem + OFF_CU);
    float* w0n  = (float*)(smem + OFF_W0N);
    float* b1s  = (float*)(smem + OFF_B1S);
    float* b2s  = (float*)(smem + OFF_B2S);
    float* oacc = (float*)(smem + OFF_OACC);

    // prologue
    {
        const float4* src = (const float4*)(x + (size_t)b * NN * 3);
        float4* dst = (float4*)xall;
        #pragma unroll
        for (int m = 0; m < 3; m++) dst[tid + m * 256] = src[tid + m * 256];
    }
    if (tid < 128) {
        float s = b0[tid];
        #pragma unroll
        for (int g = 0; g < GG; g++) s += u[b * GG + g] * W0[g * HH + tid];
        cu[tid]  = s;
        w0n[tid] = W0[8 * HH + tid];
        b1s[tid] = b1[tid];
        b2s[tid] = b2[tid];
    }
    for (int t = tid; t < 384; t += 256) oacc[t] = 0.0f;
    __syncthreads();

    // Bj frag image (dot MMA B operands)
    #pragma unroll
    for (int m = 0; m < 16; m++) {
        const int idx = tid + m * 256;
        const int jb = idx >> 5, ln = idx & 31;
        const int c2 = (ln & 3) * 2, col = jb * 8 + (ln >> 2);
        const float v0 = (c2 < 3) ? xall[col * 3 + c2] : 0.0f;
        const float v1 = (c2 + 1 < 3) ? xall[col * 3 + c2 + 1] : 0.0f;
        *(unsigned*)(smem + OFF_BJ + idx * 4) = pack2(v0, v1);
    }
    if (tid < 128) {
        const float* y = xall + (size_t)(i0 + tid) * 3;
        nrm[tid] = asqrt(y[0] * y[0] + y[1] * y[1] + y[2] * y[2]);
    }
    __syncthreads();

    // Xi dot-A fragments (m16n8k8), rows rg*32 + m*16
    unsigned xiA[2][2];
    {
        const int c2 = (lane & 3) * 2;
        #pragma unroll
        for (int m = 0; m < 2; m++) {
            const int r = rg * 32 + m * 16 + (lane >> 2);
            const float* ya = xall + (size_t)(i0 + r) * 3;
            const float* yb = xall + (size_t)(i0 + r + 8) * 3;
            xiA[m][0] = pack2((c2 < 3) ? ya[c2] : 0.0f, (c2 + 1 < 3) ? ya[c2 + 1] : 0.0f);
            xiA[m][1] = pack2((c2 < 3) ? yb[c2] : 0.0f, (c2 + 1 < 3) ? yb[c2 + 1] : 0.0f);
        }
    }

    // acc[m*8+nfl]: rows rg*32+m*16 (+r8/+8), cols cg*64+nfl*8 (+cp*2)
    float acc[16][4];
    {
        const int cp = lane & 3, r8 = lane >> 2;
        #pragma unroll
        for (int m = 0; m < 2; m++) {
            const int r1 = rg * 32 + m * 16 + r8, r2 = r1 + 8;
            const float n1 = nrm[r1], n2 = nrm[r2];
            #pragma unroll
            for (int nfl = 0; nfl < 8; nfl++) {
                const int c = cg * 64 + nfl * 8 + cp * 2;
                float* A = acc[m * 8 + nfl];
                A[0] = cu[c]     + n1 * w0n[c];
                A[1] = cu[c + 1] + n1 * w0n[c + 1];
                A[2] = cu[c]     + n2 * w0n[c];
                A[3] = cu[c + 1] + n2 * w0n[c + 1];
            }
        }
    }

    // ---------------- layer 0: pair-shared sqrt, half B traffic per warp ----------------
    const unsigned bjBase = sb + OFF_BJ + (unsigned)lane * 4 + (unsigned)cg * 128;
    const unsigned afMy   = sb + OFF_AF + (unsigned)rg * 2048 + (unsigned)cg * 512 + (unsigned)lane * 16;
    const unsigned afPa   = sb + OFF_AF + (unsigned)rg * 2048 + (unsigned)(cg ^ 1) * 512 + (unsigned)lane * 16;
    const int barid = 1 + rg;
    const uint4* Bf = (const uint4*)gBf;
    for (int cb = 0; cb < 16; cb++) {
        const unsigned bjChunk = bjBase + (unsigned)cb * 1024;
        #pragma unroll
        for (int ks16 = 0; ks16 < 4; ks16++) {
            const unsigned soff = (unsigned)(ks16 & 1) * 1024;
            // B fragments: this warp's 8 cols (4 x LDG.128)
            const uint4* bp = Bf + (size_t)(((cb * 4 + ks16) * 8 + cg * 4) * 32 + lane);
            const uint4 q0 = __ldg(bp);
            const uint4 q1 = __ldg(bp + 32);
            const uint4 q2 = __ldg(bp + 64);
            const uint4 q3 = __ldg(bp + 96);
            // own dot B frag (jb = ks16*2 + cg)
            unsigned bj;
            asm("ld.shared.b32 %0, [%1];" : "=r"(bj) : "r"(bjChunk + (unsigned)ks16 * 256));
            // dots for both row fragments vs own jb
            float d[2][4];
            d[0][0] = d[0][1] = d[0][2] = d[0][3] = 0.f;
            d[1][0] = d[1][1] = d[1][2] = d[1][3] = 0.f;
            mma16808(d[0], xiA[0][0], xiA[0][1], bj);
            mma16808(d[1], xiA[1][0], xiA[1][1], bj);
            // sqrt + pack own half of A fragments
            unsigned own[4];
            own[0] = pack2(asqrt(d[0][0]), asqrt(d[0][1]));
            own[1] = pack2(asqrt(d[0][2]), asqrt(d[0][3]));
            own[2] = pack2(asqrt(d[1][0]), asqrt(d[1][1]));
            own[3] = pack2(asqrt(d[1][2]), asqrt(d[1][3]));
            // exchange with partner warp (double-buffered slot)
            sts128(afMy + soff, own);
            barp(barid);
            unsigned part[4];
            lds128(part, afPa + soff);
            unsigned af0[4], af1[4];
            af0[0] = cg ? part[0] : own[0];
            af0[1] = cg ? part[1] : own[1];
            af0[2] = cg ? own[0]  : part[0];
            af0[3] = cg ? own[1]  : part[1];
            af1[0] = cg ? part[2] : own[2];
            af1[1] = cg ? part[3] : own[3];
            af1[2] = cg ? own[2]  : part[2];
            af1[3] = cg ? own[3]  : part[3];
            // 16 main MMAs
            mma16816(acc[0], af0, q0.x, q0.y);
            mma16816(acc[1], af0, q0.z, q0.w);
            mma16816(acc[2], af0, q1.x, q1.y);
            mma16816(acc[3], af0, q1.z, q1.w);
            mma16816(acc[4], af0, q2.x, q2.y);
            mma16816(acc[5], af0, q2.z, q2.w);
            mma16816(acc[6], af0, q3.x, q3.y);
            mma16816(acc[7], af0, q3.z, q3.w);
            mma16816(acc[8],  af1, q0.x, q0.y);
            mma16816(acc[9],  af1, q0.z, q0.w);
            mma16816(acc[10], af1, q1.x, q1.y);
            mma16816(acc[11], af1, q1.z, q1.w);
            mma16816(acc[12], af1, q2.x, q2.y);
            mma16816(acc[13], af1, q2.z, q2.w);
            mma16816(acc[14], af1, q3.x, q3.y);
            mma16816(acc[15], af1, q3.z, q3.w);
        }
    }
    __syncthreads();   // all warps done reading Bj/AF before H overwrites

    // layer MMA: A from smem H (ldsm), B fragments via LDG (own col half)
    auto layer_mma = [&](const uint4* Wf) {
        #pragma unroll
        for (int kt = 0; kt < 8; kt++) {
            const uint4* bp = Wf + (size_t)((kt * 8 + cg * 4) * 32 + lane);
            const uint4 q0 = __ldg(bp);
            const uint4 q1 = __ldg(bp + 32);
            const uint4 q2 = __ldg(bp + 64);
            const uint4 q3 = __ldg(bp + 96);
            unsigned a[2][4];
            const int kc = kt * 2 + kq;
            #pragma unroll
            for (int m = 0; m < 2; m++) {
                const int i = rg * 32 + m * 16 + il;
                ldsm_x4(a[m], sb + OFF_H + i * 256 + ((unsigned)(kc ^ (i & 7)) << 4));
            }
            #pragma unroll
            for (int m = 0; m < 2; m++) {
                mma16816(acc[m * 8 + 0], a[m], q0.x, q0.y);
                mma16816(acc[m * 8 + 1], a[m], q0.z, q0.w);
                mma16816(acc[m * 8 + 2], a[m], q1.x, q1.y);
                mma16816(acc[m * 8 + 3], a[m], q1.z, q1.w);
                mma16816(acc[m * 8 + 4], a[m], q2.x, q2.y);
                mma16816(acc[m * 8 + 5], a[m], q2.z, q2.w);
                mma16816(acc[m * 8 + 6], a[m], q3.x, q3.y);
                mma16816(acc[m * 8 + 7], a[m], q3.z, q3.w);
            }
        }
    };

    // ---------------- layer 0 epilogue -> H; layer 1 ----------------
    epi_split(acc, smem + OFF_H, b1s, rg, cg, lane);
    __syncthreads();
    layer_mma((const uint4*)gW1f);
    __syncthreads();

    // ---------------- layer 1 epilogue -> H; layer 2 ----------------
    epi_split(acc, smem + OFF_H, b2s, rg, cg, lane);
    __syncthreads();
    layer_mma((const uint4*)gW2f);

    // ---------------- final contraction ----------------
    {
        const int r8 = lane >> 2;
        #pragma unroll
        for (int m = 0; m < 2; m++) {
            const int r1 = rg * 32 + m * 16 + r8, r2 = r1 + 8;
            const float* ya = xall + (size_t)(i0 + r1) * 3;
            const float* yb = xall + (size_t)(i0 + r2) * 3;
            const float x10 = ya[0], x11 = ya[1], x12 = ya[2];
            const float x20 = yb[0], x21 = yb[1], x22 = yb[2];
            #pragma unroll
            for (int nfl = 0; nfl < 8; nfl++) {
                float* A = acc[m * 8 + nfl];
                float s[6];
                s[0] = A[0] * x10 + A[2] * x20;
                s[1] = A[0] * x11 + A[2] * x21;
                s[2] = A[0] * x12 + A[2] * x22;
                s[3] = A[1] * x10 + A[3] * x20;
                s[4] = A[1] * x11 + A[3] * x21;
                s[5] = A[1] * x12 + A[3] * x22;
                #pragma unroll
                for (int q = 0; q < 6; q++) {
                    s[q] += __shfl_xor_sync(0xffffffffu, s[q], 4);
                    s[q] += __shfl_xor_sync(0xffffffffu, s[q], 8);
                    s[q] += __shfl_xor_sync(0xffffffffu, s[q], 16);
                }
                if (lane < 4) {
                    const int c = cg * 64 + nfl * 8 + lane * 2;
                    atomicAdd(&oacc[c * 3 + 0], s[0]);
                    atomicAdd(&oacc[c * 3 + 1], s[1]);
                    atomicAdd(&oacc[c * 3 + 2], s[2]);
                    atomicAdd(&oacc[(c + 1) * 3 + 0], s[3]);
                    atomicAdd(&oacc[(c + 1) * 3 + 1], s[4]);
                    atomicAdd(&oacc[(c + 1) * 3 + 2], s[5]);
                }
            }
        }
    }
    __syncthreads();
    const float inv = 1.0f / (float)NN;
    for (int t = tid; t < 384; t += 256)
        atomicAdd(out + (size_t)b * 384 + t, oacc[t] * inv);
}

// ---------------------------------------------------------------------------
extern "C" void kernel_launch(void* const* d_in, const int* in_sizes, int n_in,
                              void* d_out, int out_size) {
    const float* x  = (const float*)d_in[0];
    const float* u  = (const float*)d_in[1];
    const float* W0 = (const float*)d_in[2];
    const float* b0 = (const float*)d_in[3];
    const float* W1 = (const float*)d_in[4];
    const float* b1 = (const float*)d_in[5];
    const float* W2 = (const float*)d_in[6];
    const float* b2 = (const float*)d_in[7];
    float* out = (float*)d_out;

    cudaFuncSetAttribute(k_main, cudaFuncAttributeMaxDynamicSharedMemorySize, SMEM_BYTES);

    k_prep<<<368, 256>>>(W0, W1, W2, out);
    k_main<<<BB * (NN / 128), 256, SMEM_BYTES>>>(x, u, W0, b0, b1, b2, out);
}

// round 14
// speedup vs baseline: 1.6071x; 1.6071x over previous
#include <cuda_runtime.h>
#include <cuda_fp16.h>

#define BB 32
#define NN 1024
#define GG 8
#define HH 128

// ---- prepped B operands in EXACT mma fragment order ----
// entry (ck, nfp, lane) = 16B = {b0(nf0), b1(nf0), b0(nf0+1), b1(nf0+1)},
// nf0 = 2*nfp; b0 lane l = {B[ck*16+2*(l&3)][c], B[..+1][c]}, c = nfp*16+(l>>2); b1: k+8.
__device__ __align__(16) unsigned gBf[65536];   // W0 dots rows (256KB)
__device__ __align__(16) unsigned gW1f[8192];   // 32KB
__device__ __align__(16) unsigned gW2f[8192];

// ---- smem map (bytes) ----
#define OFF_BJ   0        // dot B-frag image 16KB (layer0; overlaps H)
#define OFF_H    0        // h plane (128x128 fp16, 256B rows) 32KB (layer phase)
#define OFF_XALL 32768    // x[b] fp32 [1024][3]
#define OFF_NRM  45056
#define OFF_CU   45568
#define OFF_W0N  46080
#define OFF_B1S  46592
#define OFF_B2S  47104
#define OFF_OACC 47616    // fp32 [128][3]
#define SMEM_BYTES 49152

// ---------------- helpers ----------------
__device__ __forceinline__ unsigned smem_u32(const void* p) {
    unsigned a;
    asm("{ .reg .u64 t; cvta.to.shared.u64 t, %1; cvt.u32.u64 %0, t; }" : "=r"(a) : "l"(p));
    return a;
}
__device__ __forceinline__ void ldsm_x4(unsigned* r, unsigned a) {
    asm volatile("ldmatrix.sync.aligned.m8n8.x4.shared.b16 {%0,%1,%2,%3}, [%4];"
                 : "=r"(r[0]), "=r"(r[1]), "=r"(r[2]), "=r"(r[3]) : "r"(a));
}
__device__ __forceinline__ void mma16816(float* d, const unsigned* a, unsigned b0, unsigned b1) {
    asm volatile(
        "mma.sync.aligned.m16n8k16.row.col.f32.f16.f16.f32 "
        "{%0,%1,%2,%3}, {%4,%5,%6,%7}, {%8,%9}, {%0,%1,%2,%3};"
        : "+f"(d[0]), "+f"(d[1]), "+f"(d[2]), "+f"(d[3])
        : "r"(a[0]), "r"(a[1]), "r"(a[2]), "r"(a[3]), "r"(b0), "r"(b1));
}
__device__ __forceinline__ void mma16808(float* d, unsigned a0, unsigned a1, unsigned b0) {
    asm volatile(
        "mma.sync.aligned.m16n8k8.row.col.f32.f16.f16.f32 "
        "{%0,%1,%2,%3}, {%4,%5}, {%6}, {%0,%1,%2,%3};"
        : "+f"(d[0]), "+f"(d[1]), "+f"(d[2]), "+f"(d[3])
        : "r"(a0), "r"(a1), "r"(b0));
}
__device__ __forceinline__ float asqrt(float v) {
    float r;
    asm("sqrt.approx.f32 %0, %1;" : "=f"(r) : "f"(v));
    return r;
}
__device__ __forceinline__ float leaky(float v) { return v > 0.0f ? v : 0.01f * v; }
__device__ __forceinline__ unsigned short h16(float v) {
    __half h = __float2half_rn(v);
    return *(unsigned short*)&h;
}
__device__ __forceinline__ unsigned pack2(float a, float b) {
    __half2 h = __floats2half2_rn(a, b);
    return *(unsigned*)&h;
}
__device__ __forceinline__ unsigned ldss(unsigned a) {
    unsigned v;
    asm("ld.shared.b32 %0, [%1];" : "=r"(v) : "r"(a));
    return v;
}

// Epilogue (8x1): leaky + fp16 into h plane (256B rows), re-init acc with bias.
__device__ __forceinline__ void epi_split(float (&acc)[16][4], unsigned char* dH,
                                          const float* nb, int w, int lane) {
    const int cp = lane & 3, r8 = lane >> 2;
    const int r1 = w * 16 + r8, r2 = r1 + 8;
    #pragma unroll
    for (int nfl = 0; nfl < 16; nfl++) {
        float* A = acc[nfl];
        const int c = nfl * 8 + cp * 2;
        unsigned short a0 = h16(leaky(A[0])), a1 = h16(leaky(A[1]));
        unsigned short a2 = h16(leaky(A[2])), a3 = h16(leaky(A[3]));
        const unsigned o1 = r1 * 256 + ((unsigned)(((c >> 3) ^ (r1 & 7))) << 4) + (c & 7) * 2;
        const unsigned o2 = r2 * 256 + ((unsigned)(((c >> 3) ^ (r2 & 7))) << 4) + (c & 7) * 2;
        *(unsigned*)(dH + o1) = (unsigned)a0 | ((unsigned)a1 << 16);
        *(unsigned*)(dH + o2) = (unsigned)a2 | ((unsigned)a3 << 16);
        A[0] = nb[c]; A[1] = nb[c + 1]; A[2] = nb[c]; A[3] = nb[c + 1];
    }
}

// ---------------------------------------------------------------------------
// Prep (+ output zero): rewrite weights into mma B-fragment order.
__global__ void k_prep(const float* __restrict__ W0, const float* __restrict__ W1,
                       const float* __restrict__ W2, float* __restrict__ out) {
    const int idx = blockIdx.x * 256 + threadIdx.x;
    const float* src; unsigned* dst; int t;
    if (idx < 65536)      { src = W0 + 9 * HH; dst = gBf;  t = idx; }
    else if (idx < 73728) { src = W1;          dst = gW1f; t = idx - 65536; }
    else if (idx < 81920) { src = W2;          dst = gW2f; t = idx - 73728; }
    else {
        int z = idx - 81920;
        if (z < BB * HH * 3) out[z] = 0.0f;
        return;
    }
    const int e = t >> 2, wsel = t & 3;
    const int ck = e >> 8, nfp = (e >> 5) & 7, l = e & 31;
    const int k0  = ck * 16 + 2 * (l & 3) + ((wsel & 1) ? 8 : 0);
    const int col = nfp * 16 + ((wsel >> 1) ? 8 : 0) + (l >> 2);
    const float v0 = src[(size_t)k0 * HH + col];
    const float v1 = src[(size_t)(k0 + 1) * HH + col];
    dst[t] = (unsigned)h16(v0) | ((unsigned)h16(v1) << 16);
}

// ---------------------------------------------------------------------------
__global__ void __launch_bounds__(256, 2)
k_main(const float* __restrict__ x, const float* __restrict__ u,
       const float* __restrict__ W0, const float* __restrict__ b0,
       const float* __restrict__ b1, const float* __restrict__ b2,
       float* __restrict__ out)
{
    extern __shared__ __align__(1024) unsigned char smem[];
    const unsigned sb = smem_u32(smem);
    const int tid = threadIdx.x, w = tid >> 5, lane = tid & 31;
    const int b = blockIdx.x >> 3, i0 = (blockIdx.x & 7) * 128;
    const int il = lane & 15, kq = lane >> 4;

    float* xall = (float*)(smem + OFF_XALL);
    float* nrm  = (float*)(smem + OFF_NRM);
    float* cu   = (float*)(smem + OFF_CU);
    float* w0n  = (float*)(smem + OFF_W0N);
    float* b1s  = (float*)(smem + OFF_B1S);
    float* b2s  = (float*)(smem + OFF_B2S);
    float* oacc = (float*)(smem + OFF_OACC);

    // prologue: whole-batch x into smem, biases, cu
    {
        const float4* src = (const float4*)(x + (size_t)b * NN * 3);
        float4* dst = (float4*)xall;
        #pragma unroll
        for (int m = 0; m < 3; m++) dst[tid + m * 256] = src[tid + m * 256];
    }
    if (tid < 128) {
        float s = b0[tid];
        #pragma unroll
        for (int g = 0; g < GG; g++) s += u[b * GG + g] * W0[g * HH + tid];
        cu[tid]  = s;
        w0n[tid] = W0[8 * HH + tid];
        b1s[tid] = b1[tid];
        b2s[tid] = b2[tid];
    }
    for (int t = tid; t < 384; t += 256) oacc[t] = 0.0f;
    __syncthreads();

    // Bj frag image (dot MMA B operands): jblock jb, lane ln -> half2 of X coords
    #pragma unroll
    for (int m = 0; m < 16; m++) {
        const int idx = tid + m * 256;            // 0..4095
        const int jb = idx >> 5, ln = idx & 31;
        const int c2 = (ln & 3) * 2, col = jb * 8 + (ln >> 2);
        const float v0 = (c2 < 3) ? xall[col * 3 + c2] : 0.0f;
        const float v1 = (c2 + 1 < 3) ? xall[col * 3 + c2 + 1] : 0.0f;
        *(unsigned*)(smem + OFF_BJ + idx * 4) = pack2(v0, v1);
    }
    if (tid < 128) {
        const float* y = xall + (size_t)(i0 + tid) * 3;
        nrm[tid] = asqrt(y[0] * y[0] + y[1] * y[1] + y[2] * y[2]);
    }
    __syncthreads();

    // Xi dot-A fragment (m16n8k8): warp w owns rows w*16..w*16+15
    unsigned xiA[2];
    {
        const int c2 = (lane & 3) * 2;
        const int r = w * 16 + (lane >> 2);
        const float* ya = xall + (size_t)(i0 + r) * 3;
        const float* yb = xall + (size_t)(i0 + r + 8) * 3;
        xiA[0] = pack2((c2 < 3) ? ya[c2] : 0.0f, (c2 + 1 < 3) ? ya[c2 + 1] : 0.0f);
        xiA[1] = pack2((c2 < 3) ? yb[c2] : 0.0f, (c2 + 1 < 3) ? yb[c2 + 1] : 0.0f);
    }

    // acc[nfl][4]: rows w*16 (+r8/+8), cols nfl*8 (+cp*2); init bias + u/norm features
    float acc[16][4];
    {
        const int cp = lane & 3, r8 = lane >> 2;
        const int r1 = w * 16 + r8, r2 = r1 + 8;
        const float n1 = nrm[r1], n2 = nrm[r2];
        #pragma unroll
        for (int nfl = 0; nfl < 16; nfl++) {
            const int c = nfl * 8 + cp * 2;
            float* A = acc[nfl];
            A[0] = cu[c]     + n1 * w0n[c];
            A[1] = cu[c + 1] + n1 * w0n[c + 1];
            A[2] = cu[c]     + n2 * w0n[c];
            A[3] = cu[c + 1] + n2 * w0n[c + 1];
        }
    }

    // ---------------- layer 0: barrier-free, software-pipelined ----------------
    const unsigned bjBase = sb + OFF_BJ + (unsigned)lane * 4;
    const uint4* Bf = (const uint4*)gBf;
    unsigned bj0 = ldss(bjBase);
    unsigned bj1 = ldss(bjBase + 128);
    #pragma unroll 4
    for (int it = 0; it < 64; it++) {
        const uint4* bp = Bf + (size_t)it * 256 + lane;
        // first half of B fragments
        const uint4 q0 = __ldg(bp);
        const uint4 q1 = __ldg(bp + 32);
        const uint4 q2 = __ldg(bp + 64);
        const uint4 q3 = __ldg(bp + 96);
        // dots (16 rows x 16 j) on current bj
        float d[2][4];
        d[0][0] = d[0][1] = d[0][2] = d[0][3] = 0.f;
        d[1][0] = d[1][1] = d[1][2] = d[1][3] = 0.f;
        mma16808(d[0], xiA[0], xiA[1], bj0);
        mma16808(d[1], xiA[0], xiA[1], bj1);
        // prefetch next iteration's bj (harmless over-read on last iter)
        const unsigned bjn = bjBase + (unsigned)(it + 1) * 256;
        const unsigned bj0n = ldss(bjn);
        const unsigned bj1n = ldss(bjn + 128);
        // second half of B fragments (overlaps MUFU chain)
        const uint4 q4 = __ldg(bp + 128);
        const uint4 q5 = __ldg(bp + 160);
        const uint4 q6 = __ldg(bp + 192);
        const uint4 q7 = __ldg(bp + 224);
        // sqrt + pack -> A fragment (m16n8k16)
        unsigned af[4];
        af[0] = pack2(asqrt(d[0][0]), asqrt(d[0][1]));
        af[1] = pack2(asqrt(d[0][2]), asqrt(d[0][3]));
        af[2] = pack2(asqrt(d[1][0]), asqrt(d[1][1]));
        af[3] = pack2(asqrt(d[1][2]), asqrt(d[1][3]));
        // 16 main MMAs
        mma16816(acc[0], af, q0.x, q0.y);
        mma16816(acc[1], af, q0.z, q0.w);
        mma16816(acc[2], af, q1.x, q1.y);
        mma16816(acc[3], af, q1.z, q1.w);
        mma16816(acc[4], af, q2.x, q2.y);
        mma16816(acc[5], af, q2.z, q2.w);
        mma16816(acc[6], af, q3.x, q3.y);
        mma16816(acc[7], af, q3.z, q3.w);
        mma16816(acc[8],  af, q4.x, q4.y);
        mma16816(acc[9],  af, q4.z, q4.w);
        mma16816(acc[10], af, q5.x, q5.y);
        mma16816(acc[11], af, q5.z, q5.w);
        mma16816(acc[12], af, q6.x, q6.y);
        mma16816(acc[13], af, q6.z, q6.w);
        mma16816(acc[14], af, q7.x, q7.y);
        mma16816(acc[15], af, q7.z, q7.w);
        bj0 = bj0n; bj1 = bj1n;
    }
    __syncthreads();   // all warps done reading Bj before H overwrites it

    // layer MMA: A from smem H (ldsm), B fragments via LDG
    auto layer_mma = [&](const uint4* Wf) {
        #pragma unroll
        for (int kt = 0; kt < 8; kt++) {
            const uint4* bp = Wf + (size_t)(kt * 8 * 32 + lane);
            uint4 q[8];
            #pragma unroll
            for (int p = 0; p < 8; p++) q[p] = __ldg(bp + p * 32);
            unsigned a[4];
            const int kc = kt * 2 + kq;
            const int i = w * 16 + il;
            ldsm_x4(a, sb + OFF_H + i * 256 + ((unsigned)(kc ^ (i & 7)) << 4));
            #pragma unroll
            for (int p = 0; p < 8; p++) {
                mma16816(acc[p * 2 + 0], a, q[p].x, q[p].y);
                mma16816(acc[p * 2 + 1], a, q[p].z, q[p].w);
            }
        }
    };

    // ---------------- layer 0 epilogue -> H; layer 1 ----------------
    epi_split(acc, smem + OFF_H, b1s, w, lane);
    __syncthreads();
    layer_mma((const uint4*)gW1f);
    __syncthreads();

    // ---------------- layer 1 epilogue -> H; layer 2 ----------------
    epi_split(acc, smem + OFF_H, b2s, w, lane);
    __syncthreads();
    layer_mma((const uint4*)gW2f);

    // ---------------- final contraction ----------------
    {
        const int r8 = lane >> 2;
        const int r1 = w * 16 + r8, r2 = r1 + 8;
        const float* ya = xall + (size_t)(i0 + r1) * 3;
        const float* yb = xall + (size_t)(i0 + r2) * 3;
        const float x10 = ya[0], x11 = ya[1], x12 = ya[2];
        const float x20 = yb[0], x21 = yb[1], x22 = yb[2];
        #pragma unroll
        for (int nfl = 0; nfl < 16; nfl++) {
            float* A = acc[nfl];
            float s[6];
            s[0] = A[0] * x10 + A[2] * x20;
            s[1] = A[0] * x11 + A[2] * x21;
            s[2] = A[0] * x12 + A[2] * x22;
            s[3] = A[1] * x10 + A[3] * x20;
            s[4] = A[1] * x11 + A[3] * x21;
            s[5] = A[1] * x12 + A[3] * x22;
            #pragma unroll
            for (int q = 0; q < 6; q++) {
                s[q] += __shfl_xor_sync(0xffffffffu, s[q], 4);
                s[q] += __shfl_xor_sync(0xffffffffu, s[q], 8);
                s[q] += __shfl_xor_sync(0xffffffffu, s[q], 16);
            }
            if (lane < 4) {
                const int c = nfl * 8 + lane * 2;
                atomicAdd(&oacc[c * 3 + 0], s[0]);
                atomicAdd(&oacc[c * 3 + 1], s[1]);
                atomicAdd(&oacc[c * 3 + 2], s[2]);
                atomicAdd(&oacc[(c + 1) * 3 + 0], s[3]);
                atomicAdd(&oacc[(c + 1) * 3 + 1], s[4]);
                atomicAdd(&oacc[(c + 1) * 3 + 2], s[5]);
            }
        }
    }
    __syncthreads();
    const float inv = 1.0f / (float)NN;
    for (int t = tid; t < 384; t += 256)
        atomicAdd(out + (size_t)b * 384 + t, oacc[t] * inv);
}

// ---------------------------------------------------------------------------
extern "C" void kernel_launch(void* const* d_in, const int* in_sizes, int n_in,
                              void* d_out, int out_size) {
    const float* x  = (const float*)d_in[0];
    const float* u  = (const float*)d_in[1];
    const float* W0 = (const float*)d_in[2];
    const float* b0 = (const float*)d_in[3];
    const float* W1 = (const float*)d_in[4];
    const float* b1 = (const float*)d_in[5];
    const float* W2 = (const float*)d_in[6];
    const float* b2 = (const float*)d_in[7];
    float* out = (float*)d_out;

    cudaFuncSetAttribute(k_main, cudaFuncAttributeMaxDynamicSharedMemorySize, SMEM_BYTES);

    k_prep<<<368, 256>>>(W0, W1, W2, out);
    k_main<<<BB * (NN / 128), 256, SMEM_BYTES>>>(x, u, W0, b0, b1, b2, out);
}